// round 8
// baseline (speedup 1.0000x reference)
#include <cuda_runtime.h>
#include <cuda_fp16.h>
#include <cstdint>

// Problem dims
#define NM 64
#define NK 4096
#define NW 14336
#define NTILE 128           // N columns per CTA
#define KC 128              // K per chunk
#define NITER 32            // NK/KC
#define NBLK 112            // NW/NTILE
#define THREADS 512
#define NCONS 256           // consumer threads (warps 0-7); producers are warps 8-15
#define STAGES 4

// SMEM: 4 buffers x (W fp16 32KB [k-major 128x256B, swizzled] + A fp16 16KB)
#define BUFSZ 49152
#define XOFF  32768
#define SM_MB (STAGES * BUFSZ)          // 4 x {full,empty} mbarrier pairs (16B each)
#define SMEM_TOTAL (SM_MB + STAGES * 16)

// Global scratch: pre-swizzled fp16 x image (32 chunks x 16KB) + rowsum
__device__ __align__(16) unsigned char g_ximg[NITER * 16384];
__device__ float g_rowsum[NM];

// ---------------- helpers ----------------
__device__ __forceinline__ uint32_t smem_u32(const void* p) {
    uint32_t a;
    asm("{ .reg .u64 t; cvta.to.shared.u64 t, %1; cvt.u32.u64 %0, t; }" : "=r"(a) : "l"(p));
    return a;
}

#define MBARRIER_INIT(addr, cnt) \
    asm volatile("mbarrier.init.shared.b64 [%0], %1;" :: "r"((uint32_t)(addr)), "r"((uint32_t)(cnt)) : "memory")

#define MBARRIER_ARRIVE(addr) \
    asm volatile("mbarrier.arrive.shared.b64 _, [%0];" :: "r"((uint32_t)(addr)) : "memory")

#define MBARRIER_WAIT_PARITY(mbar, par) do {                                        \
    uint32_t _m = (uint32_t)(mbar); uint32_t _p = (uint32_t)(par); uint32_t _d;     \
    asm volatile("{ .reg .pred p;\n"                                                \
        "mbarrier.try_wait.parity.acquire.cta.shared::cta.b64 p, [%1], %2;\n"       \
        "selp.b32 %0, 1, 0, p; }"                                                   \
        : "=r"(_d) : "r"(_m), "r"(_p) : "memory");                                  \
    if (!_d) {                                                                      \
        asm volatile("{ .reg .pred P1;\n"                                           \
            "WL_%=:\n"                                                              \
            "mbarrier.try_wait.parity.acquire.cta.shared::cta.b64 P1, [%0], %1, 0x989680;\n" \
            "@P1 bra.uni WD_%=;\n"                                                  \
            "bra.uni WL_%=;\n"                                                      \
            "WD_%=: }" :: "r"(_m), "r"(_p) : "memory");                             \
    }                                                                               \
} while (0)

__device__ __forceinline__ void ldmatrix_x4(uint32_t* r, uint32_t addr) {
    asm volatile("ldmatrix.sync.aligned.m8n8.x4.shared.b16 {%0,%1,%2,%3}, [%4];"
        : "=r"(r[0]), "=r"(r[1]), "=r"(r[2]), "=r"(r[3]) : "r"(addr));
}
__device__ __forceinline__ void ldmatrix_x4_trans(uint32_t* r, uint32_t addr) {
    asm volatile("ldmatrix.sync.aligned.m8n8.x4.trans.shared.b16 {%0,%1,%2,%3}, [%4];"
        : "=r"(r[0]), "=r"(r[1]), "=r"(r[2]), "=r"(r[3]) : "r"(addr));
}
__device__ __forceinline__ void sts64(uint32_t addr, uint32_t a, uint32_t b) {
    asm volatile("st.shared.v2.b32 [%0], {%1,%2};" :: "r"(addr), "r"(a), "r"(b) : "memory");
}
__device__ __forceinline__ void sts128(uint32_t addr, uint4 v) {
    asm volatile("st.shared.v4.b32 [%0], {%1,%2,%3,%4};"
        :: "r"(addr), "r"(v.x), "r"(v.y), "r"(v.z), "r"(v.w) : "memory");
}
__device__ __forceinline__ uint32_t pack_f16x2(int lo, int hi) {
    float fl, fh; uint32_t d;
    asm("cvt.rn.f32.s32 %0, %1;" : "=f"(fl) : "r"(lo));
    asm("cvt.rn.f32.s32 %0, %1;" : "=f"(fh) : "r"(hi));
    asm("cvt.rn.f16x2.f32 %0, %1, %2;" : "=r"(d) : "f"(fh), "f"(fl));
    return d;
}
__device__ __forceinline__ void mma16816(float* d, const uint32_t* a, const uint32_t* b) {
    asm volatile(
        "mma.sync.aligned.m16n8k16.row.col.f32.f16.f16.f32 "
        "{%0,%1,%2,%3}, {%4,%5,%6,%7}, {%8,%9}, {%0,%1,%2,%3};"
        : "+f"(d[0]), "+f"(d[1]), "+f"(d[2]), "+f"(d[3])
        : "r"(a[0]), "r"(a[1]), "r"(a[2]), "r"(a[3]), "r"(b[0]), "r"(b[1]));
}

// ---------------- prep kernel: x -> fp16 image (swizzled) + rowsum ----------------
// image layout per chunk c (16KB): addr = c*16384 + m*256 + ((kl*2) ^ ((m&7)<<4))
__global__ void prep(const float* __restrict__ x) {
    __shared__ float red[16];
    const int m = blockIdx.x;
    const int t = threadIdx.x;          // 512 threads, each handles 8 k
    const int k = t * 8;
    const float4* xp = reinterpret_cast<const float4*>(x + (size_t)m * NK + k);
    float4 a = xp[0], b = xp[1];
    float v[8] = {a.x, a.y, a.z, a.w, b.x, b.y, b.z, b.w};
    __align__(16) __half h[8];
    float s = 0.f;
#pragma unroll
    for (int i = 0; i < 8; i++) { h[i] = __float2half_rn(v[i]); s += v[i]; }
    const int c = k >> 7;
    const int kl = k & 127;
    uint32_t off = (uint32_t)c * 16384u + (uint32_t)m * 256u
                 + (((uint32_t)kl * 2u) ^ (((uint32_t)m & 7u) << 4));
    *reinterpret_cast<uint4*>(g_ximg + off) = *reinterpret_cast<uint4*>(h);
#pragma unroll
    for (int o = 16; o; o >>= 1) s += __shfl_xor_sync(0xffffffffu, s, o);
    if ((t & 31) == 0) red[t >> 5] = s;
    __syncthreads();
    if (t < 16) {
        float r = red[t];
#pragma unroll
        for (int o = 8; o; o >>= 1) r += __shfl_xor_sync(0xffffu, r, o);
        if (t == 0) g_rowsum[m] = r;
    }
}

// ---------------- main kernel ----------------
__global__ __launch_bounds__(THREADS, 1) void wqmm_main(
    const int* __restrict__ w,
    const float* __restrict__ scale,
    const float* __restrict__ offs,
    const float* __restrict__ bias,
    float* __restrict__ out)
{
    extern __shared__ char smem[];
    const uint32_t sb = smem_u32(smem);
    const int tid = threadIdx.x;
    const int wid = tid >> 5;
    const int lane = tid & 31;
    const int n0 = blockIdx.x * NTILE;

    if (tid == 0) {
#pragma unroll
        for (int s = 0; s < STAGES; s++) {
            MBARRIER_INIT(sb + SM_MB + s * 16 + 0, NCONS);   // full[s]: 256 producer arrivals
            MBARRIER_INIT(sb + SM_MB + s * 16 + 8, NCONS);   // empty[s]: 256 consumer arrivals
        }
    }
    __syncthreads();

    if (tid >= NCONS) {
        // ================= producers (warps 8-15) =================
        const int pt = tid - NCONS;     // 0..255
        const int pw = pt >> 5;         // 0..7 -> 16 k-rows each
        const int pl = pt & 31;         // lane -> 4 n each (n = 4*pl..4*pl+3)
        const uint4* aimg = reinterpret_cast<const uint4*>(g_ximg);

        for (int it = 0; it < NITER; ++it) {
            const int b = it & 3;
            const uint32_t wb = sb + (uint32_t)b * BUFSZ;
            const uint32_t xb = wb + XOFF;
            const int kb0 = it * KC + pw * 16;

            // stage first 8 W rows + A chunk (issue LDGs before the empty-wait)
            int4 wv[8];
#pragma unroll
            for (int j = 0; j < 8; j++)
                wv[j] = __ldcs(reinterpret_cast<const int4*>(w + (size_t)(kb0 + j) * NW + n0) + pl);
            uint4 av[4];
            const uint4* asrc = aimg + (size_t)it * 1024 + (size_t)pt * 4;
#pragma unroll
            for (int i = 0; i < 4; i++) av[i] = __ldg(asrc + i);

            // wait for buffer free: completion #(it>>2) of empty[b] -> parity ((it>>2)+1)&1
            MBARRIER_WAIT_PARITY(sb + SM_MB + b * 16 + 8, ((it >> 2) + 1) & 1);

#pragma unroll
            for (int j = 0; j < 8; j++) {
                const int k = pw * 16 + j;
                uint32_t lo = pack_f16x2(wv[j].x, wv[j].y);
                uint32_t hi = pack_f16x2(wv[j].z, wv[j].w);
                sts64(wb + (uint32_t)k * 256 + (((uint32_t)pl * 8) ^ (((uint32_t)j & 7) << 4)), lo, hi);
            }
#pragma unroll
            for (int i = 0; i < 4; i++) sts128(xb + (uint32_t)pt * 64 + i * 16, av[i]);

            // second 8 W rows
#pragma unroll
            for (int j = 0; j < 8; j++)
                wv[j] = __ldcs(reinterpret_cast<const int4*>(w + (size_t)(kb0 + 8 + j) * NW + n0) + pl);
#pragma unroll
            for (int j = 0; j < 8; j++) {
                const int k = pw * 16 + 8 + j;
                uint32_t lo = pack_f16x2(wv[j].x, wv[j].y);
                uint32_t hi = pack_f16x2(wv[j].z, wv[j].w);
                sts64(wb + (uint32_t)k * 256 + (((uint32_t)pl * 8) ^ (((uint32_t)j & 7) << 4)), lo, hi);
            }
            MBARRIER_ARRIVE(sb + SM_MB + b * 16);   // full[b]
        }
        return;
    }

    // ================= consumers (warps 0-7): 2m x 4n grid, m32 x n32 tiles =================
    const int mw = wid >> 2;            // 0..1
    const int nw = wid & 3;             // 0..3
    const int g = lane >> 2;
    const int tg = lane & 3;

    // A ldmatrix addressing (proven in R7)
    const uint32_t aoff = (uint32_t)(mw * 32 + (lane & 8) + (lane & 7)) * 256u;
    const uint32_t aswx = ((uint32_t)(lane & 7)) << 4;
    const uint32_t akq = ((uint32_t)((lane >> 4) & 1)) * 16u;

    // B trans-ldmatrix addressing: lane l -> matrix oct=l>>3, row r=l&7
    const uint32_t oct = (uint32_t)(lane >> 3);
    const uint32_t br = (uint32_t)(lane & 7);
    const uint32_t bofs = br * 256u + (((uint32_t)(nw * 64) + oct * 16u) ^ (br << 4));

    float acc[2][4][4];
#pragma unroll
    for (int i = 0; i < 2; i++)
#pragma unroll
        for (int j = 0; j < 4; j++)
#pragma unroll
            for (int q = 0; q < 4; q++) acc[i][j][q] = 0.f;

    for (int it = 0; it < NITER; ++it) {
        const int b = it & 3;
        // wait for fill completion #(it>>2 + 1) -> parity (it>>2)&1
        MBARRIER_WAIT_PARITY(sb + SM_MB + b * 16, (it >> 2) & 1);

        const uint32_t wb = sb + (uint32_t)b * BUFSZ;
        const uint32_t xb = wb + XOFF;

#pragma unroll
        for (int ks = 0; ks < 8; ks++) {
            uint32_t a0[4], a1[4];
            const uint32_t xaddr = xb + aoff + (((uint32_t)(ks * 32) + akq) ^ aswx);
            ldmatrix_x4(a0, xaddr);
            ldmatrix_x4(a1, xaddr + 4096);

            uint32_t bl[4], bh[4];
            const uint32_t baddr = wb + (uint32_t)ks * 4096u + bofs;
            ldmatrix_x4_trans(bl, baddr);           // b0 fragments, n-octets 0..3
            ldmatrix_x4_trans(bh, baddr + 2048);    // b1 fragments (k+8)

#pragma unroll
            for (int nt = 0; nt < 4; nt++) {
                uint32_t bfr[2] = {bl[nt], bh[nt]};
                mma16816(acc[0][nt], a0, bfr);
                mma16816(acc[1][nt], a1, bfr);
            }
        }
        MBARRIER_ARRIVE(sb + SM_MB + b * 16 + 8);   // empty[b]
    }

    // ---- epilogue: out = scale*acc + scale*offset*rowsum + bias ----
#pragma unroll
    for (int nt = 0; nt < 4; nt++) {
        const int n = n0 + nw * 32 + nt * 8 + tg * 2;
        const float s0 = scale[n], s1 = scale[n + 1];
        const float t0 = s0 * offs[n], t1 = s1 * offs[n + 1];
        const float b0 = bias[n], b1 = bias[n + 1];
#pragma unroll
        for (int mt = 0; mt < 2; mt++) {
            const int m = mw * 32 + mt * 16 + g;
            const float r0 = g_rowsum[m];
            const float r1 = g_rowsum[m + 8];
            float2 v0, v1;
            v0.x = fmaf(acc[mt][nt][0], s0, fmaf(t0, r0, b0));
            v0.y = fmaf(acc[mt][nt][1], s1, fmaf(t1, r0, b1));
            v1.x = fmaf(acc[mt][nt][2], s0, fmaf(t0, r1, b0));
            v1.y = fmaf(acc[mt][nt][3], s1, fmaf(t1, r1, b1));
            *reinterpret_cast<float2*>(out + (size_t)m * NW + n) = v0;
            *reinterpret_cast<float2*>(out + (size_t)(m + 8) * NW + n) = v1;
        }
    }
}

// ---------------- launch ----------------
extern "C" void kernel_launch(void* const* d_in, const int* in_sizes, int n_in,
                              void* d_out, int out_size) {
    const float* x     = (const float*)d_in[0];
    const int*   w     = (const int*)d_in[1];
    const float* scale = (const float*)d_in[2];
    const float* offs  = (const float*)d_in[3];
    const float* bias  = (const float*)d_in[4];
    float* out = (float*)d_out;

    cudaFuncSetAttribute(wqmm_main, cudaFuncAttributeMaxDynamicSharedMemorySize, SMEM_TOTAL);

    prep<<<NM, 512>>>(x);
    wqmm_main<<<NBLK, THREADS, SMEM_TOTAL>>>(w, scale, offs, bias, out);
}

// round 9
// speedup vs baseline: 1.0659x; 1.0659x over previous
#include <cuda_runtime.h>
#include <cuda_fp16.h>
#include <cstdint>

// Problem dims
#define NM 64
#define NK 4096
#define NW 14336
#define NTILE 128           // N columns per CTA
#define KC 128              // K per chunk
#define NITER 32            // NK/KC
#define NBLK 112            // NW/NTILE
#define THREADS 512
#define NCONS 256           // consumer threads (warps 0-7); producers are warps 8-15
#define STAGES 4

// SMEM: 4 buffers x (W fp16 32KB [k-major 128x256B, swizzled] + A fp16 16KB)
#define BUFSZ 49152
#define XOFF  32768
#define SM_MB (STAGES * BUFSZ)          // 4 x {full,empty} mbarrier pairs (16B each)
#define SMEM_TOTAL (SM_MB + STAGES * 16)

// Global scratch: pre-swizzled fp16 x image (32 chunks x 16KB) + rowsum
__device__ __align__(16) unsigned char g_ximg[NITER * 16384];
__device__ float g_rowsum[NM];

// ---------------- helpers ----------------
__device__ __forceinline__ uint32_t smem_u32(const void* p) {
    uint32_t a;
    asm("{ .reg .u64 t; cvta.to.shared.u64 t, %1; cvt.u32.u64 %0, t; }" : "=r"(a) : "l"(p));
    return a;
}

#define MBARRIER_INIT(addr, cnt) \
    asm volatile("mbarrier.init.shared.b64 [%0], %1;" :: "r"((uint32_t)(addr)), "r"((uint32_t)(cnt)) : "memory")

#define MBARRIER_ARRIVE(addr) \
    asm volatile("mbarrier.arrive.release.cta.shared::cta.b64 _, [%0];" :: "r"((uint32_t)(addr)) : "memory")

#define MBARRIER_WAIT_PARITY(mbar, par) do {                                        \
    uint32_t _m = (uint32_t)(mbar); uint32_t _p = (uint32_t)(par); uint32_t _d;     \
    asm volatile("{ .reg .pred p;\n"                                                \
        "mbarrier.try_wait.parity.acquire.cta.shared::cta.b64 p, [%1], %2;\n"       \
        "selp.b32 %0, 1, 0, p; }"                                                   \
        : "=r"(_d) : "r"(_m), "r"(_p) : "memory");                                  \
    if (!_d) {                                                                      \
        asm volatile("{ .reg .pred P1;\n"                                           \
            "WL_%=:\n"                                                              \
            "mbarrier.try_wait.parity.acquire.cta.shared::cta.b64 P1, [%0], %1, 0x989680;\n" \
            "@P1 bra.uni WD_%=;\n"                                                  \
            "bra.uni WL_%=;\n"                                                      \
            "WD_%=: }" :: "r"(_m), "r"(_p) : "memory");                             \
    }                                                                               \
} while (0)

__device__ __forceinline__ void ldmatrix_x4(uint32_t* r, uint32_t addr) {
    asm volatile("ldmatrix.sync.aligned.m8n8.x4.shared.b16 {%0,%1,%2,%3}, [%4];"
        : "=r"(r[0]), "=r"(r[1]), "=r"(r[2]), "=r"(r[3]) : "r"(addr));
}
__device__ __forceinline__ void ldmatrix_x4_trans(uint32_t* r, uint32_t addr) {
    asm volatile("ldmatrix.sync.aligned.m8n8.x4.trans.shared.b16 {%0,%1,%2,%3}, [%4];"
        : "=r"(r[0]), "=r"(r[1]), "=r"(r[2]), "=r"(r[3]) : "r"(addr));
}
__device__ __forceinline__ void sts64(uint32_t addr, uint32_t a, uint32_t b) {
    asm volatile("st.shared.v2.b32 [%0], {%1,%2};" :: "r"(addr), "r"(a), "r"(b) : "memory");
}
__device__ __forceinline__ void sts128(uint32_t addr, uint4 v) {
    asm volatile("st.shared.v4.b32 [%0], {%1,%2,%3,%4};"
        :: "r"(addr), "r"(v.x), "r"(v.y), "r"(v.z), "r"(v.w) : "memory");
}
__device__ __forceinline__ uint32_t pack_f16x2(int lo, int hi) {
    float fl, fh; uint32_t d;
    asm("cvt.rn.f32.s32 %0, %1;" : "=f"(fl) : "r"(lo));
    asm("cvt.rn.f32.s32 %0, %1;" : "=f"(fh) : "r"(hi));
    asm("cvt.rn.f16x2.f32 %0, %1, %2;" : "=r"(d) : "f"(fh), "f"(fl));
    return d;
}
__device__ __forceinline__ void mma16816(float* d, const uint32_t* a, const uint32_t* b) {
    asm volatile(
        "mma.sync.aligned.m16n8k16.row.col.f32.f16.f16.f32 "
        "{%0,%1,%2,%3}, {%4,%5,%6,%7}, {%8,%9}, {%0,%1,%2,%3};"
        : "+f"(d[0]), "+f"(d[1]), "+f"(d[2]), "+f"(d[3])
        : "r"(a[0]), "r"(a[1]), "r"(a[2]), "r"(a[3]), "r"(b[0]), "r"(b[1]));
}

// ---------------- prep kernel: x -> fp16 image (swizzled) + rowsum ----------------
// image layout per chunk c (16KB): addr = c*16384 + m*256 + ((kl*2) ^ ((m&7)<<4))
__global__ void prep(const float* __restrict__ x) {
    __shared__ float red[16];
    const int m = blockIdx.x;
    const int t = threadIdx.x;          // 512 threads, each handles 8 k
    const int k = t * 8;
    const float4* xp = reinterpret_cast<const float4*>(x + (size_t)m * NK + k);
    float4 a = xp[0], b = xp[1];
    float v[8] = {a.x, a.y, a.z, a.w, b.x, b.y, b.z, b.w};
    __align__(16) __half h[8];
    float s = 0.f;
#pragma unroll
    for (int i = 0; i < 8; i++) { h[i] = __float2half_rn(v[i]); s += v[i]; }
    const int c = k >> 7;
    const int kl = k & 127;
    uint32_t off = (uint32_t)c * 16384u + (uint32_t)m * 256u
                 + (((uint32_t)kl * 2u) ^ (((uint32_t)m & 7u) << 4));
    *reinterpret_cast<uint4*>(g_ximg + off) = *reinterpret_cast<uint4*>(h);
#pragma unroll
    for (int o = 16; o; o >>= 1) s += __shfl_xor_sync(0xffffffffu, s, o);
    if ((t & 31) == 0) red[t >> 5] = s;
    __syncthreads();
    if (t < 16) {
        float r = red[t];
#pragma unroll
        for (int o = 8; o; o >>= 1) r += __shfl_xor_sync(0xffffu, r, o);
        if (t == 0) g_rowsum[m] = r;
    }
}

// ---------------- main kernel ----------------
__global__ __launch_bounds__(THREADS, 1) void wqmm_main(
    const int* __restrict__ w,
    const float* __restrict__ scale,
    const float* __restrict__ offs,
    const float* __restrict__ bias,
    float* __restrict__ out)
{
    extern __shared__ char smem[];
    const uint32_t sb = smem_u32(smem);
    const int tid = threadIdx.x;
    const int wid = tid >> 5;
    const int lane = tid & 31;
    const int n0 = blockIdx.x * NTILE;

    if (tid == 0) {
#pragma unroll
        for (int s = 0; s < STAGES; s++) {
            MBARRIER_INIT(sb + SM_MB + s * 16 + 0, 8);   // full[s]: 8 producer-warp arrivals
            MBARRIER_INIT(sb + SM_MB + s * 16 + 8, 8);   // empty[s]: 8 consumer-warp arrivals
        }
    }
    __syncthreads();

    if (tid >= NCONS) {
        // ================= producers (warps 8-15) =================
        const int pt = tid - NCONS;     // 0..255
        const int pw = pt >> 5;         // 0..7 -> 16 k-rows each
        const int pl = pt & 31;         // lane -> 4 n each
        const uint4* aimg = reinterpret_cast<const uint4*>(g_ximg);
        const uint32_t stsbase = (uint32_t)(pw * 16) * 256u + ((uint32_t)pl * 8);

        for (int it = 0; it < NITER; ++it) {
            const int b = it & 3;
            const uint32_t wb = sb + (uint32_t)b * BUFSZ;
            const uint32_t xb = wb + XOFF;
            const int kb0 = it * KC + pw * 16;

            // issue ALL global loads for this chunk up front (latency pipelining)
            int4 wv[16];
#pragma unroll
            for (int j = 0; j < 16; j++)
                wv[j] = __ldcs(reinterpret_cast<const int4*>(w + (size_t)(kb0 + j) * NW + n0) + pl);
            uint4 av[4];
            const uint4* asrc = aimg + (size_t)it * 1024 + (size_t)pt * 4;
#pragma unroll
            for (int i = 0; i < 4; i++) av[i] = __ldg(asrc + i);

            // wait for buffer free: completion #(it>>2) of empty[b] -> parity ((it>>2)+1)&1
            MBARRIER_WAIT_PARITY(sb + SM_MB + b * 16 + 8, ((it >> 2) + 1) & 1);

#pragma unroll
            for (int j = 0; j < 16; j++) {
                uint32_t lo = pack_f16x2(wv[j].x, wv[j].y);
                uint32_t hi = pack_f16x2(wv[j].z, wv[j].w);
                sts64(wb + ((stsbase + (uint32_t)j * 256) ^ (((uint32_t)j & 7) << 4)), lo, hi);
            }
#pragma unroll
            for (int i = 0; i < 4; i++) sts128(xb + (uint32_t)pt * 64 + i * 16, av[i]);

            __syncwarp();
            if (lane == 0) MBARRIER_ARRIVE(sb + SM_MB + b * 16);   // full[b]
        }
        return;
    }

    // ================= consumers (warps 0-7): 2m x 4n grid, m32 x n32 tiles =================
    const int mw = wid >> 2;            // 0..1
    const int nw = wid & 3;             // 0..3
    const int g = lane >> 2;
    const int tg = lane & 3;

    // A ldmatrix addressing
    const uint32_t aoff = (uint32_t)(mw * 32 + (lane & 8) + (lane & 7)) * 256u;
    const uint32_t aswx = ((uint32_t)(lane & 7)) << 4;
    const uint32_t akq = ((uint32_t)((lane >> 4) & 1)) * 16u;

    // B trans-ldmatrix addressing: lane l -> matrix oct=l>>3, row r=l&7
    const uint32_t oct = (uint32_t)(lane >> 3);
    const uint32_t br = (uint32_t)(lane & 7);
    const uint32_t bofs = br * 256u + (((uint32_t)(nw * 64) + oct * 16u) ^ (br << 4));

    float acc[2][4][4];
#pragma unroll
    for (int i = 0; i < 2; i++)
#pragma unroll
        for (int j = 0; j < 4; j++)
#pragma unroll
            for (int q = 0; q < 4; q++) acc[i][j][q] = 0.f;

    for (int it = 0; it < NITER; ++it) {
        const int b = it & 3;
        // wait for fill completion #(it>>2 + 1) -> parity (it>>2)&1
        MBARRIER_WAIT_PARITY(sb + SM_MB + b * 16, (it >> 2) & 1);

        const uint32_t wb = sb + (uint32_t)b * BUFSZ;
        const uint32_t xb = wb + XOFF;

#pragma unroll
        for (int ks = 0; ks < 8; ks++) {
            uint32_t a0[4], a1[4];
            const uint32_t xaddr = xb + aoff + (((uint32_t)(ks * 32) + akq) ^ aswx);
            ldmatrix_x4(a0, xaddr);
            ldmatrix_x4(a1, xaddr + 4096);

            uint32_t bl[4], bh[4];
            const uint32_t baddr = wb + (uint32_t)ks * 4096u + bofs;
            ldmatrix_x4_trans(bl, baddr);           // b0 fragments, n-octets 0..3
            ldmatrix_x4_trans(bh, baddr + 2048);    // b1 fragments (k+8)

#pragma unroll
            for (int nt = 0; nt < 4; nt++) {
                uint32_t bfr[2] = {bl[nt], bh[nt]};
                mma16816(acc[0][nt], a0, bfr);
                mma16816(acc[1][nt], a1, bfr);
            }
        }
        __syncwarp();
        if (lane == 0) MBARRIER_ARRIVE(sb + SM_MB + b * 16 + 8);   // empty[b]
    }

    // ---- epilogue: out = scale*acc + scale*offset*rowsum + bias ----
#pragma unroll
    for (int nt = 0; nt < 4; nt++) {
        const int n = n0 + nw * 32 + nt * 8 + tg * 2;
        const float s0 = scale[n], s1 = scale[n + 1];
        const float t0 = s0 * offs[n], t1 = s1 * offs[n + 1];
        const float b0 = bias[n], b1 = bias[n + 1];
#pragma unroll
        for (int mt = 0; mt < 2; mt++) {
            const int m = mw * 32 + mt * 16 + g;
            const float r0 = g_rowsum[m];
            const float r1 = g_rowsum[m + 8];
            float2 v0, v1;
            v0.x = fmaf(acc[mt][nt][0], s0, fmaf(t0, r0, b0));
            v0.y = fmaf(acc[mt][nt][1], s1, fmaf(t1, r0, b1));
            v1.x = fmaf(acc[mt][nt][2], s0, fmaf(t0, r1, b0));
            v1.y = fmaf(acc[mt][nt][3], s1, fmaf(t1, r1, b1));
            *reinterpret_cast<float2*>(out + (size_t)m * NW + n) = v0;
            *reinterpret_cast<float2*>(out + (size_t)(m + 8) * NW + n) = v1;
        }
    }
}

// ---------------- launch ----------------
extern "C" void kernel_launch(void* const* d_in, const int* in_sizes, int n_in,
                              void* d_out, int out_size) {
    const float* x     = (const float*)d_in[0];
    const int*   w     = (const int*)d_in[1];
    const float* scale = (const float*)d_in[2];
    const float* offs  = (const float*)d_in[3];
    const float* bias  = (const float*)d_in[4];
    float* out = (float*)d_out;

    cudaFuncSetAttribute(wqmm_main, cudaFuncAttributeMaxDynamicSharedMemorySize, SMEM_TOTAL);

    prep<<<NM, 512>>>(x);
    wqmm_main<<<NBLK, THREADS, SMEM_TOTAL>>>(w, scale, offs, bias, out);
}

// round 10
// speedup vs baseline: 1.3518x; 1.2683x over previous
#include <cuda_runtime.h>
#include <cuda.h>
#include <cuda_fp16.h>
#include <cstdint>

// Problem dims
#define NM 64
#define NK 4096
#define NW 14336
#define NTILE 128           // N columns per CTA
#define KC2 64              // K per stage (half-chunk)
#define NIT2 64             // NK/KC2
#define NBLK 112            // NW/NTILE
#define THREADS 256
#define STAGES 4

// SMEM: 4 stages x (W int32 32KB [4 boxes of 32n x 64k, SW128] + A fp16 8KB)
#define BUFSZ 40960
#define XOFF  32768
#define SM_MB (STAGES * BUFSZ)          // 4 full-barriers (8B each)
#define SMEM_TOTAL (SM_MB + STAGES * 8)

// Global scratch: pre-swizzled fp16 x image (64 half-chunks x 8KB) + partial rowsums
__device__ __align__(16) unsigned char g_ximg[NIT2 * 8192];
__device__ __align__(16) float g_rs4[NM * 4];

// ---------------- helpers ----------------
__device__ __forceinline__ uint32_t smem_u32(const void* p) {
    uint32_t a;
    asm("{ .reg .u64 t; cvta.to.shared.u64 t, %1; cvt.u32.u64 %0, t; }" : "=r"(a) : "l"(p));
    return a;
}

#define MBARRIER_INIT(addr, cnt) \
    asm volatile("mbarrier.init.shared.b64 [%0], %1;" :: "r"((uint32_t)(addr)), "r"((uint32_t)(cnt)) : "memory")

#define MBARRIER_EXPECT_TX(addr, bytes) \
    asm volatile("mbarrier.arrive.expect_tx.shared.b64 _, [%0], %1;" \
        :: "r"((uint32_t)(addr)), "r"((uint32_t)(bytes)) : "memory")

#define MBARRIER_WAIT_PARITY(mbar, par) do {                                        \
    uint32_t _m = (uint32_t)(mbar); uint32_t _p = (uint32_t)(par); uint32_t _d;     \
    asm volatile("{ .reg .pred p;\n"                                                \
        "mbarrier.try_wait.parity.acquire.cta.shared::cta.b64 p, [%1], %2;\n"       \
        "selp.b32 %0, 1, 0, p; }"                                                   \
        : "=r"(_d) : "r"(_m), "r"(_p) : "memory");                                  \
    if (!_d) {                                                                      \
        asm volatile("{ .reg .pred P1;\n"                                           \
            "WL_%=:\n"                                                              \
            "mbarrier.try_wait.parity.acquire.cta.shared::cta.b64 P1, [%0], %1, 0x989680;\n" \
            "@P1 bra.uni WD_%=;\n"                                                  \
            "bra.uni WL_%=;\n"                                                      \
            "WD_%=: }" :: "r"(_m), "r"(_p) : "memory");                             \
    }                                                                               \
} while (0)

__device__ __forceinline__ void tma_2d(uint32_t dst, const void* map, int cx, int cy, uint32_t mbar) {
    asm volatile(
        "cp.async.bulk.tensor.2d.shared::cluster.global.tile.mbarrier::complete_tx::bytes "
        "[%0], [%1, {%2, %3}], [%4];"
        :: "r"(dst), "l"(map), "r"(cx), "r"(cy), "r"(mbar) : "memory");
}
__device__ __forceinline__ void bulk_g2s(uint32_t dst, const void* src, uint32_t bytes, uint32_t mbar) {
    asm volatile(
        "cp.async.bulk.shared::cluster.global.mbarrier::complete_tx::bytes "
        "[%0], [%1], %2, [%3];"
        :: "r"(dst), "l"(src), "r"(bytes), "r"(mbar) : "memory");
}
__device__ __forceinline__ void ldmatrix_x4(uint32_t* r, uint32_t addr) {
    asm volatile("ldmatrix.sync.aligned.m8n8.x4.shared.b16 {%0,%1,%2,%3}, [%4];"
        : "=r"(r[0]), "=r"(r[1]), "=r"(r[2]), "=r"(r[3]) : "r"(addr));
}
__device__ __forceinline__ uint32_t lds32(uint32_t addr) {
    uint32_t v;
    asm volatile("ld.shared.b32 %0, [%1];" : "=r"(v) : "r"(addr));
    return v;
}
__device__ __forceinline__ uint32_t pack_f16x2(int lo, int hi) {
    float fl, fh; uint32_t d;
    asm("cvt.rn.f32.s32 %0, %1;" : "=f"(fl) : "r"(lo));
    asm("cvt.rn.f32.s32 %0, %1;" : "=f"(fh) : "r"(hi));
    asm("cvt.rn.f16x2.f32 %0, %1, %2;" : "=r"(d) : "f"(fh), "f"(fl));
    return d;
}
__device__ __forceinline__ void mma16816(float* d, const uint32_t* a, const uint32_t* b) {
    asm volatile(
        "mma.sync.aligned.m16n8k16.row.col.f32.f16.f16.f32 "
        "{%0,%1,%2,%3}, {%4,%5,%6,%7}, {%8,%9}, {%0,%1,%2,%3};"
        : "+f"(d[0]), "+f"(d[1]), "+f"(d[2]), "+f"(d[3])
        : "r"(a[0]), "r"(a[1]), "r"(a[2]), "r"(a[3]), "r"(b[0]), "r"(b[1]));
}

// ---------------- prep: x -> fp16 image (half-chunk layout) + partial rowsums ----------------
// half-chunk hc (8KB): addr = hc*8192 + m*128 + (((k&63)*2) ^ ((m&7)<<4))
__global__ void prep(const float* __restrict__ x) {
    __shared__ float red[4];
    const int m = blockIdx.x >> 2;
    const int kq = blockIdx.x & 3;
    const int t = threadIdx.x;              // 128 threads x 8 k
    const int k = kq * 1024 + t * 8;
    const float4* xp = reinterpret_cast<const float4*>(x + (size_t)m * NK + k);
    float4 a = xp[0], b = xp[1];
    float v[8] = {a.x, a.y, a.z, a.w, b.x, b.y, b.z, b.w};
    __align__(16) __half h[8];
    float s = 0.f;
#pragma unroll
    for (int i = 0; i < 8; i++) { h[i] = __float2half_rn(v[i]); s += v[i]; }
    uint32_t off = (uint32_t)(k >> 6) * 8192u + (uint32_t)m * 128u
                 + ((((uint32_t)k & 63u) * 2u) ^ (((uint32_t)m & 7u) << 4));
    *reinterpret_cast<uint4*>(g_ximg + off) = *reinterpret_cast<uint4*>(h);
#pragma unroll
    for (int o = 16; o; o >>= 1) s += __shfl_xor_sync(0xffffffffu, s, o);
    if ((t & 31) == 0) red[t >> 5] = s;
    __syncthreads();
    if (t == 0) g_rs4[m * 4 + kq] = red[0] + red[1] + red[2] + red[3];
}

// ---------------- main kernel ----------------
__global__ __launch_bounds__(THREADS, 1) void wqmm_main(
    const __grid_constant__ CUtensorMap tmw,
    const float* __restrict__ scale,
    const float* __restrict__ offs,
    const float* __restrict__ bias,
    float* __restrict__ out)
{
    extern __shared__ char smem[];
    const uint32_t sb = smem_u32(smem);
    const int tid = threadIdx.x;
    const int wid = tid >> 5;
    const int lane = tid & 31;
    const int n0 = blockIdx.x * NTILE;

    if (tid == 0) {
#pragma unroll
        for (int s = 0; s < STAGES; s++) MBARRIER_INIT(sb + SM_MB + s * 8, 1);
        asm volatile("fence.mbarrier_init.release.cluster;" ::: "memory");
    }
    __syncthreads();

    // issue loads for half-chunk it into stage it&3 (single thread)
    auto issue = [&](int it) {
        const int b = it & 3;
        const uint32_t mb = sb + SM_MB + (uint32_t)b * 8;
        const uint32_t wdst = sb + (uint32_t)b * BUFSZ;
        MBARRIER_EXPECT_TX(mb, 40960);
#pragma unroll
        for (int bx = 0; bx < 4; bx++)
            tma_2d(wdst + (uint32_t)bx * 8192, &tmw, n0 + bx * 32, it * KC2, mb);
        bulk_g2s(wdst + XOFF, g_ximg + (size_t)it * 8192, 8192, mb);
    };
    if (tid == 0) { issue(0); issue(1); issue(2); issue(3); }

    // ---- consumer addressing: (2m x 4n) grid, m32 x n32 warp tiles ----
    const int mw = wid >> 2;            // 0..1
    const int nw = wid & 3;             // 0..3 -> box nw
    const int g = lane >> 2;
    const int tg = lane & 3;

    // A ldmatrix (128B rows): row = mw*32 + (lane&8) + (lane&7)
    const uint32_t aoff = (uint32_t)(mw * 32 + (lane & 8) + (lane & 7)) * 128u;
    const uint32_t aswx = ((uint32_t)(lane & 7)) << 4;
    const uint32_t akq = ((uint32_t)((lane >> 4) & 1)) * 16u;

    // B int32 LDS offsets (within box): nl = nt*8 + g
    uint32_t c0[4], c1[4];
#pragma unroll
    for (int nt = 0; nt < 4; nt++) {
        uint32_t nl = (uint32_t)(nt * 8 + g);
        c0[nt] = (nl * 4u) ^ (((uint32_t)(tg * 2)) << 4);
        c1[nt] = (nl * 4u) ^ (((uint32_t)(tg * 2 + 1)) << 4);
    }
    const uint32_t boxoff = (uint32_t)nw * 8192u;
    const uint32_t tgrow = (uint32_t)(tg * 2) * 128u;

    float acc[2][4][4];
#pragma unroll
    for (int i = 0; i < 2; i++)
#pragma unroll
        for (int j = 0; j < 4; j++)
#pragma unroll
            for (int q = 0; q < 4; q++) acc[i][j][q] = 0.f;

    for (int it = 0; it < NIT2; ++it) {
        const int b = it & 3;
        MBARRIER_WAIT_PARITY(sb + SM_MB + b * 8, (it >> 2) & 1);

        const uint32_t wb = sb + (uint32_t)b * BUFSZ;
        const uint32_t xb = wb + XOFF;
        const uint32_t wbox = wb + boxoff;

#pragma unroll
        for (int ks = 0; ks < 4; ks++) {
            uint32_t a0[4], a1[4];
            const uint32_t xaddr = xb + aoff + (((uint32_t)(ks * 32) + akq) ^ aswx);
            ldmatrix_x4(a0, xaddr);
            ldmatrix_x4(a1, xaddr + 2048);      // +16 m-rows

            const uint32_t kb = wbox + (uint32_t)ks * 2048u + tgrow;
#pragma unroll
            for (int nt = 0; nt < 4; nt++) {
                int w00 = (int)lds32(kb + c0[nt]);          // k, n
                int w01 = (int)lds32(kb + 128 + c1[nt]);    // k+1
                int w08 = (int)lds32(kb + 1024 + c0[nt]);   // k+8
                int w09 = (int)lds32(kb + 1152 + c1[nt]);   // k+9
                uint32_t bfr[2];
                bfr[0] = pack_f16x2(w00, w01);
                bfr[1] = pack_f16x2(w08, w09);
                mma16816(acc[0][nt], a0, bfr);
                mma16816(acc[1][nt], a1, bfr);
            }
        }
        __syncthreads();
        if (tid == 0 && it + 4 < NIT2) issue(it + 4);
    }

    // ---- epilogue: out = scale*acc + scale*offset*rowsum + bias ----
#pragma unroll
    for (int nt = 0; nt < 4; nt++) {
        const int n = n0 + nw * 32 + nt * 8 + tg * 2;
        const float s0 = scale[n], s1 = scale[n + 1];
        const float t0 = s0 * offs[n], t1 = s1 * offs[n + 1];
        const float b0 = bias[n], b1 = bias[n + 1];
#pragma unroll
        for (int mt = 0; mt < 2; mt++) {
            const int m = mw * 32 + mt * 16 + g;
            const float4 ra = *reinterpret_cast<const float4*>(g_rs4 + (size_t)m * 4);
            const float4 rb = *reinterpret_cast<const float4*>(g_rs4 + (size_t)(m + 8) * 4);
            const float r0 = (ra.x + ra.y) + (ra.z + ra.w);
            const float r1 = (rb.x + rb.y) + (rb.z + rb.w);
            float2 v0, v1;
            v0.x = fmaf(acc[mt][nt][0], s0, fmaf(t0, r0, b0));
            v0.y = fmaf(acc[mt][nt][1], s1, fmaf(t1, r0, b1));
            v1.x = fmaf(acc[mt][nt][2], s0, fmaf(t0, r1, b0));
            v1.y = fmaf(acc[mt][nt][3], s1, fmaf(t1, r1, b1));
            *reinterpret_cast<float2*>(out + (size_t)m * NW + n) = v0;
            *reinterpret_cast<float2*>(out + (size_t)(m + 8) * NW + n) = v1;
        }
    }
}

// ---------------- launch ----------------
typedef CUresult (*EncodeFn)(CUtensorMap*, CUtensorMapDataType, cuuint32_t, void*,
    const cuuint64_t*, const cuuint64_t*, const cuuint32_t*, const cuuint32_t*,
    CUtensorMapInterleave, CUtensorMapSwizzle, CUtensorMapL2promotion, CUtensorMapFloatOOBfill);

extern "C" void kernel_launch(void* const* d_in, const int* in_sizes, int n_in,
                              void* d_out, int out_size) {
    const float* x     = (const float*)d_in[0];
    void*        w     = (void*)d_in[1];
    const float* scale = (const float*)d_in[2];
    const float* offs  = (const float*)d_in[3];
    const float* bias  = (const float*)d_in[4];
    float* out = (float*)d_out;

    void* sym = nullptr;
    cudaDriverEntryPointQueryResult qr;
#if CUDART_VERSION >= 12050
    cudaGetDriverEntryPointByVersion("cuTensorMapEncodeTiled", &sym, 12000, cudaEnableDefault, &qr);
#else
    cudaGetDriverEntryPoint("cuTensorMapEncodeTiled", &sym, cudaEnableDefault, &qr);
#endif
    EncodeFn enc = (EncodeFn)sym;

    CUtensorMap tmw;
    cuuint64_t dims[2]    = {(cuuint64_t)NW, (cuuint64_t)NK};
    cuuint64_t strides[1] = {(cuuint64_t)NW * 4};
    cuuint32_t box[2]     = {32u, 64u};
    cuuint32_t es[2]      = {1u, 1u};
    enc(&tmw, CU_TENSOR_MAP_DATA_TYPE_UINT32, 2, w, dims, strides, box, es,
        CU_TENSOR_MAP_INTERLEAVE_NONE, CU_TENSOR_MAP_SWIZZLE_128B,
        CU_TENSOR_MAP_L2_PROMOTION_L2_128B, CU_TENSOR_MAP_FLOAT_OOB_FILL_NONE);

    cudaFuncSetAttribute(wqmm_main, cudaFuncAttributeMaxDynamicSharedMemorySize, SMEM_TOTAL);

    prep<<<NM * 4, 128>>>(x);
    wqmm_main<<<NBLK, THREADS, SMEM_TOTAL>>>(tmw, scale, offs, bias, out);
}